// round 14
// baseline (speedup 1.0000x reference)
#include <cuda_runtime.h>
#include <cuda_fp16.h>
#include <math.h>
#include <stdint.h>

// ---------------- problem constants ----------------
#define DMODEL 1024
#define NH     16
#define HD     64
#define BATCH  2
#define SEQ    2048
#define MTOK   (BATCH*SEQ)        // 4096

// ---------------- scratch (device globals, all fp16) ----------------
__device__ __half g_x[MTOK*DMODEL];
__device__ __half g_q[BATCH*NH*SEQ*HD];
__device__ __half g_k[BATCH*NH*SEQ*HD];   // compacted rows per (b,h); tail zero
__device__ __half g_v[BATCH*NH*SEQ*HD];   // compacted rows per (b,h); tail zero
__device__ __half g_att[BATCH*SEQ*NH*HD];
__device__ __half g_wt[4*DMODEL*DMODEL];  // qwT,kwT,vwT,owT [N][K]
__device__ int    g_cidx[BATCH*SEQ];
__device__ int    g_cnt[BATCH];

// ---------------- helpers ----------------
__device__ __forceinline__ uint32_t f2h2(float a, float b) {
    __half2 h = __floats2half2_rn(a, b);
    return *reinterpret_cast<uint32_t*>(&h);
}
__device__ __forceinline__ uint32_t smem_u32(const void* p) {
    uint32_t a;
    asm("{ .reg .u64 t; cvta.to.shared.u64 t, %1; cvt.u32.u64 %0, t; }" : "=r"(a) : "l"(p));
    return a;
}
__device__ __forceinline__ void cp16(uint32_t dst, const void* src) {
    asm volatile("cp.async.cg.shared.global [%0], [%1], 16;" :: "r"(dst), "l"(src) : "memory");
}
#define CP_COMMIT() asm volatile("cp.async.commit_group;" ::: "memory")
#define CP_WAIT1()  asm volatile("cp.async.wait_group 1;"  ::: "memory")

__device__ __forceinline__ void mma_f16(float* d, const uint32_t* a, const uint32_t* b) {
    asm volatile(
        "mma.sync.aligned.m16n8k16.row.col.f32.f16.f16.f32 "
        "{%0,%1,%2,%3}, {%4,%5,%6,%7}, {%8,%9}, {%0,%1,%2,%3};"
        : "+f"(d[0]), "+f"(d[1]), "+f"(d[2]), "+f"(d[3])
        : "r"(a[0]), "r"(a[1]), "r"(a[2]), "r"(a[3]), "r"(b[0]), "r"(b[1]));
}
__device__ __forceinline__ void ldsm_x4(uint32_t* r, uint32_t addr) {
    asm volatile("ldmatrix.sync.aligned.m8n8.x4.shared.b16 {%0,%1,%2,%3}, [%4];"
                 : "=r"(r[0]), "=r"(r[1]), "=r"(r[2]), "=r"(r[3]) : "r"(addr));
}
__device__ __forceinline__ void ldsm_x4_trans(uint32_t* r, uint32_t addr) {
    asm volatile("ldmatrix.sync.aligned.m8n8.x4.trans.shared.b16 {%0,%1,%2,%3}, [%4];"
                 : "=r"(r[0]), "=r"(r[1]), "=r"(r[2]), "=r"(r[3]) : "r"(addr));
}

// ======================================================================
// prep_all: z=0..3 -> weight transpose to fp16 [N][K];
//           z=4    -> x -> fp16; blocks 0,1 also compact mask indices.
// ======================================================================
__global__ __launch_bounds__(256)
void prep_all(const float4* __restrict__ x, const int* __restrict__ pm,
              const float* __restrict__ qw, const float* __restrict__ kw,
              const float* __restrict__ vw, const float* __restrict__ ow)
{
    const int tx = threadIdx.x, ty = threadIdx.y;       // 32 x 8
    const int z = blockIdx.z;
    if (z < 4) {
        __shared__ float tile[32][33];
        const float* src = (z == 0) ? qw : (z == 1) ? kw : (z == 2) ? vw : ow;
        __half* dst = g_wt + (size_t)z * DMODEL * DMODEL;
        const int bx = blockIdx.x * 32, by = blockIdx.y * 32;
        #pragma unroll
        for (int i = 0; i < 32; i += 8)
            tile[ty + i][tx] = src[(size_t)(by + ty + i) * DMODEL + bx + tx];
        __syncthreads();
        #pragma unroll
        for (int i = 0; i < 32; i += 8)
            dst[(size_t)(bx + ty + i) * DMODEL + by + tx] = __float2half_rn(tile[tx][ty + i]);
        return;
    }
    const int t   = ty * 32 + tx;
    const int bid = blockIdx.y * 32 + blockIdx.x;
    #pragma unroll
    for (int j = 0; j < 4; j++) {
        int i = (bid * 4 + j) * 256 + t;
        float4 v = x[i];
        reinterpret_cast<uint2*>(g_x)[i] =
            make_uint2(f2h2(v.x, v.y), f2h2(v.z, v.w));
    }
    if (bid < BATCH) {
        __shared__ int wsum[8];
        const int b = bid;
        const int* row = pm + b * SEQ;
        const int lane = t & 31, w = t >> 5;
        int flags[8], cnt = 0;
        #pragma unroll
        for (int j = 0; j < 8; j++) { flags[j] = (row[t * 8 + j] == 0); cnt += flags[j]; }
        int inc = cnt;
        #pragma unroll
        for (int d = 1; d < 32; d <<= 1) {
            int v = __shfl_up_sync(0xffffffff, inc, d);
            if (lane >= d) inc += v;
        }
        if (lane == 31) wsum[w] = inc;
        __syncthreads();
        int woff = 0;
        for (int ww = 0; ww < w; ww++) woff += wsum[ww];
        int pos = woff + inc - cnt;
        #pragma unroll
        for (int j = 0; j < 8; j++)
            if (flags[j]) g_cidx[b * SEQ + pos++] = t * 8 + j;
        if (t == 255) g_cnt[b] = woff + inc;
    }
}

// ======================================================================
// GEMM fp16 (unchanged from R13): BM=BN=128, BK=64, 3-stage cp.async,
// 8 warps (2x4), warp tile 64x32, m16n8k16, ldmatrix fragments.
// MODE 0: Q; MODE 1: out (fp32); MODE 2: K/V compacted + zero tail.
// ======================================================================
#define GT 256
#define GSTG 3
#define ASTRIDE 36
#define TILE_W  (128 * ASTRIDE)       // 4608 words
#define STAGE_W (2 * TILE_W)          // 9216 words
#define GEMM_SMEM (GSTG * STAGE_W * 4)  // 110592 B

template<int MODE>
__device__ __forceinline__ void gemm_body(const __half* __restrict__ A,
                                          const __half* __restrict__ BT,
                                          const float* __restrict__ bias,
                                          void* __restrict__ Cv)
{
    extern __shared__ uint32_t sm[];
    const uint32_t sb = smem_u32(sm);

    const int t     = threadIdx.x;
    const int lane  = t & 31;
    const int warp  = t >> 5;
    const int warpM = warp >> 2;
    const int warpN = warp & 3;
    const int lr    = lane >> 2;
    const int lc    = lane & 3;
    const int m0    = blockIdx.y * 128;
    const int n0    = blockIdx.x * 128;

    int n_b = SEQ;
    int bB  = 0;
    if (MODE == 2) {
        bB  = m0 >> 11;
        n_b = g_cnt[bB];
        const int n_pad = (n_b + 63) & ~63;
        if ((m0 & (SEQ - 1)) >= n_pad) return;
    }

    const int lrow16 = lane & 15;
    const int lkw    = ((lane >> 4) & 1) * 4;

    const int lrow[4] = { (t+0)>>3, (t+256)>>3, (t+512)>>3, (t+768)>>3 };
    const int lsg [4] = { (t+0)&7,  (t+256)&7,  (t+512)&7,  (t+768)&7  };

    const __half* aptr[4];
    #pragma unroll
    for (int i = 0; i < 4; i++) {
        if (MODE == 2) {
            int s = (m0 & (SEQ - 1)) + lrow[i];
            int sc = s < n_b - 1 ? s : n_b - 1;
            int ridx = g_cidx[bB * SEQ + sc];
            aptr[i] = A + (size_t)(bB * SEQ + ridx) * DMODEL;
        } else {
            aptr[i] = A + (size_t)(m0 + lrow[i]) * DMODEL;
        }
    }

    float acc[4][4][4];
    #pragma unroll
    for (int mt = 0; mt < 4; mt++)
        #pragma unroll
        for (int nt = 0; nt < 4; nt++)
            #pragma unroll
            for (int c = 0; c < 4; c++) acc[mt][nt][c] = 0.f;

    #pragma unroll
    for (int s = 0; s < 2; s++) {
        uint32_t base = sb + s * STAGE_W * 4;
        #pragma unroll
        for (int i = 0; i < 4; i++) {
            cp16(base + (lrow[i] * ASTRIDE + lsg[i] * 4) * 4,
                 aptr[i] + s * 64 + lsg[i] * 8);
            cp16(base + (TILE_W + lrow[i] * ASTRIDE + lsg[i] * 4) * 4,
                 &BT[(size_t)(n0 + lrow[i]) * DMODEL + s * 64 + lsg[i] * 8]);
        }
        CP_COMMIT();
    }

    const int NCH = DMODEL / 64;
    for (int c = 0; c < NCH; c++) {
        CP_WAIT1();
        __syncthreads();

        if (c + 2 < NCH) {
            uint32_t base = sb + ((c + 2) % GSTG) * STAGE_W * 4;
            int k0 = (c + 2) * 64;
            #pragma unroll
            for (int i = 0; i < 4; i++) {
                cp16(base + (lrow[i] * ASTRIDE + lsg[i] * 4) * 4,
                     aptr[i] + k0 + lsg[i] * 8);
                cp16(base + (TILE_W + lrow[i] * ASTRIDE + lsg[i] * 4) * 4,
                     &BT[(size_t)(n0 + lrow[i]) * DMODEL + k0 + lsg[i] * 8]);
            }
        }
        CP_COMMIT();

        const uint32_t asb = sb + ((c % GSTG) * STAGE_W) * 4;
        const uint32_t bsb = asb + TILE_W * 4;
        #pragma unroll
        for (int p = 0; p < 4; p++) {
            uint32_t af[4][4], bq[2][4];
            #pragma unroll
            for (int mt = 0; mt < 4; mt++)
                ldsm_x4(af[mt], asb + ((warpM * 64 + mt * 16 + lrow16) * ASTRIDE
                                       + p * 8 + lkw) * 4);
            #pragma unroll
            for (int ntp = 0; ntp < 2; ntp++)
                ldsm_x4(bq[ntp], bsb + ((warpN * 32 + ntp * 16 + lrow16) * ASTRIDE
                                        + p * 8 + lkw) * 4);
            #pragma unroll
            for (int mt = 0; mt < 4; mt++) {
                #pragma unroll
                for (int ntp = 0; ntp < 2; ntp++) {
                    uint32_t b0[2] = { bq[ntp][0], bq[ntp][2] };
                    uint32_t b1[2] = { bq[ntp][1], bq[ntp][3] };
                    mma_f16(acc[mt][2 * ntp + 0], af[mt], b0);
                    mma_f16(acc[mt][2 * ntp + 1], af[mt], b1);
                }
            }
        }
    }

    #pragma unroll
    for (int mt = 0; mt < 4; mt++) {
        #pragma unroll
        for (int nt = 0; nt < 4; nt++) {
            int n = n0 + warpN * 32 + nt * 8 + 2 * lc;
            float bia0 = bias[n], bia1 = bias[n + 1];
            #pragma unroll
            for (int half_ = 0; half_ < 2; half_++) {
                int m = m0 + warpM * 64 + mt * 16 + lr + half_ * 8;
                float v0 = acc[mt][nt][half_ * 2 + 0] + bia0;
                float v1 = acc[mt][nt][half_ * 2 + 1] + bia1;
                if (MODE == 1) {
                    float* C = (float*)Cv;
                    *reinterpret_cast<float2*>(&C[(size_t)m * DMODEL + n]) = make_float2(v0, v1);
                } else {
                    int b = m >> 11, s = m & (SEQ - 1);
                    if (MODE == 2 && s >= n_b) { v0 = 0.f; v1 = 0.f; }
                    int h = n >> 6,  d = n & (HD - 1);
                    __half* C = (__half*)Cv;
                    *reinterpret_cast<uint32_t*>(
                        &C[(((size_t)(b * NH + h) * SEQ) + s) * HD + d]) = f2h2(v0, v1);
                }
            }
        }
    }
}

__global__ __launch_bounds__(GT, 2)
void qkv_kernel(const float* __restrict__ qb, const float* __restrict__ kb,
                const float* __restrict__ vb)
{
    if (blockIdx.z == 0)      gemm_body<0>(g_x, g_wt + 0 * DMODEL * DMODEL, qb, g_q);
    else if (blockIdx.z == 1) gemm_body<2>(g_x, g_wt + 1 * DMODEL * DMODEL, kb, g_k);
    else                      gemm_body<2>(g_x, g_wt + 2 * DMODEL * DMODEL, vb, g_v);
}

__global__ __launch_bounds__(GT, 2)
void out_kernel(const float* __restrict__ ob, float* __restrict__ out)
{
    gemm_body<1>(g_att, g_wt + 3 * DMODEL * DMODEL, ob, out);
}

// ======================================================================
// FlashAttention fp16 over DENSE compacted K/V.
// Smem tiles of 128 keys (2 slots), computed as 2 sub-passes of 64 keys
// -> half the barrier/prefetch events per key vs R13; register footprint
// unchanged. Tail keys (up to 128-align) are zero rows -> p = 0 exactly.
// ======================================================================
#define BQ   128
#define BKT  128                        // keys per smem tile
#define W_QP 0                          // 128*36 = 4608 words
#define W_KS 4608                       // 2 slots x 128*36 = 9216
#define W_VS 13824                      // 2 slots x 128*36 = 9216
#define ATTN_W 23040
#define ATTN_SMEM_BYTES (ATTN_W * 4)    // 92160 B

__global__ __launch_bounds__(256, 2)
void attn_kernel(const int* __restrict__ pmask)
{
    extern __shared__ uint32_t sm[];
    const uint32_t sb = smem_u32(sm);
    uint32_t* QP = sm + W_QP;

    const int bh = blockIdx.y;
    const int b  = bh >> 4;
    const int h  = bh & (NH - 1);
    const int q0 = blockIdx.x * BQ;
    const int t    = threadIdx.x;
    const int lane = t & 31;
    const int wid  = t >> 5;
    const int lr   = lane >> 2;
    const int lc   = lane & 3;
    const int lrow16 = lane & 15;
    const int lkw    = ((lane >> 4) & 1) * 4;

    const __half* qg = g_q + (size_t)bh * SEQ * HD;
    const __half* kg = g_k + (size_t)bh * SEQ * HD;
    const __half* vg = g_v + (size_t)bh * SEQ * HD;
    const int     n_b  = g_cnt[b];
    const int     NT   = (n_b + BKT - 1) / BKT;

    // K/V tile: 128 rows x 8 segs = 1024 cp16 / 256 thr = 4 each
    const int trow[4] = { (t+0)>>3, (t+256)>>3, (t+512)>>3, (t+768)>>3 };
    const int tsg [4] = { ((t+0)&7)*8, ((t+256)&7)*8, ((t+512)&7)*8, ((t+768)&7)*8 };

    // ---- prologue: Q + tile0, tile1 ----
    #pragma unroll
    for (int i = 0; i < 4; i++) {
        int f = t + i * 256, row = f >> 3, ho = (f & 7) * 8;
        cp16(sb + (W_QP + row * 36 + (ho >> 1)) * 4, &qg[(size_t)(q0 + row) * HD + ho]);
    }
    #pragma unroll
    for (int j = 0; j < 4; j++) {
        cp16(sb + (W_KS + trow[j] * 36 + (tsg[j] >> 1)) * 4, &kg[(size_t)trow[j] * HD + tsg[j]]);
        cp16(sb + (W_VS + trow[j] * 36 + (tsg[j] >> 1)) * 4, &vg[(size_t)trow[j] * HD + tsg[j]]);
    }
    CP_COMMIT();
    if (NT > 1) {
        #pragma unroll
        for (int j = 0; j < 4; j++) {
            int key = BKT + trow[j];
            cp16(sb + (W_KS + 4608 + trow[j] * 36 + (tsg[j] >> 1)) * 4, &kg[(size_t)key * HD + tsg[j]]);
            cp16(sb + (W_VS + 4608 + trow[j] * 36 + (tsg[j] >> 1)) * 4, &vg[(size_t)key * HD + tsg[j]]);
        }
    }
    CP_COMMIT();
    CP_WAIT1();
    __syncthreads();

    uint32_t qf[4][4];
    {
        uint32_t qpb = sb + W_QP * 4;
        #pragma unroll
        for (int ks = 0; ks < 4; ks++)
            ldsm_x4(qf[ks], qpb + ((wid * 16 + lrow16) * 36 + ks * 8 + lkw) * 4);
    }

    const int vmi = lane >> 3, vli = lane & 7;
    const int vrow = ((vmi & 1) ? 8 : 0) + vli;
    const int vcol = (vmi >> 1) ? 4 : 0;

    float o[8][4];
    #pragma unroll
    for (int nt = 0; nt < 8; nt++)
        #pragma unroll
        for (int c = 0; c < 4; c++) o[nt][c] = 0.f;
    float l0 = 0.f, l1 = 0.f;

    for (int i = 0; i < NT; i++) {
        const int slot = i & 1;

        // two 64-key sub-passes over the loaded 128-key tile
        #pragma unroll
        for (int sub = 0; sub < 2; sub++) {
            const int kb = i * BKT + sub * 64;
            const uint32_t ksb = sb + (W_KS + slot * 4608 + sub * 64 * 36) * 4;
            const uint32_t vsb = sb + (W_VS + slot * 4608 + sub * 64 * 36) * 4;

            float s[8][4];
            #pragma unroll
            for (int nt = 0; nt < 8; nt++)
                #pragma unroll
                for (int c = 0; c < 4; c++) s[nt][c] = 0.f;
            #pragma unroll
            for (int ks = 0; ks < 4; ks++) {
                uint32_t kq[4][4];
                #pragma unroll
                for (int ntp = 0; ntp < 4; ntp++)
                    ldsm_x4(kq[ntp], ksb + ((ntp * 16 + lrow16) * 36 + ks * 8 + lkw) * 4);
                #pragma unroll
                for (int ntp = 0; ntp < 4; ntp++) {
                    uint32_t b0[2] = { kq[ntp][0], kq[ntp][2] };
                    uint32_t b1[2] = { kq[ntp][1], kq[ntp][3] };
                    mma_f16(s[2 * ntp + 0], qf[ks], b0);
                    mma_f16(s[2 * ntp + 1], qf[ks], b1);
                }
            }

            int r = wid * 16 + lr;
            #pragma unroll
            for (int nt = 0; nt < 8; nt++) {
                float ma0 = (kb + nt * 8 + 2 * lc     < n_b) ? 0.0f : -1e30f;
                float ma1 = (kb + nt * 8 + 2 * lc + 1 < n_b) ? 0.0f : -1e30f;
                float p0 = __expf(fmaf(s[nt][0], 0.125f, ma0));
                float p1 = __expf(fmaf(s[nt][1], 0.125f, ma1));
                float p2 = __expf(fmaf(s[nt][2], 0.125f, ma0));
                float p3 = __expf(fmaf(s[nt][3], 0.125f, ma1));
                l0 += p0 + p1;
                l1 += p2 + p3;
                QP[(r + 0) * 36 + nt * 4 + lc] = f2h2(p0, p1);
                QP[(r + 8) * 36 + nt * 4 + lc] = f2h2(p2, p3);
            }
            __syncwarp();

            uint32_t qpb = sb + W_QP * 4;
            #pragma unroll
            for (int kt = 0; kt < 4; kt++) {
                uint32_t af[4];
                ldsm_x4(af, qpb + ((wid * 16 + lrow16) * 36 + kt * 8 + lkw) * 4);
                #pragma unroll
                for (int ntp = 0; ntp < 4; ntp++) {
                    uint32_t vbr[4];
                    uint32_t addr = vsb + (((kt * 16 + vrow) * 36) + ntp * 8 + vcol) * 4;
                    ldsm_x4_trans(vbr, addr);
                    mma_f16(o[2 * ntp + 0], af, vbr + 0);
                    mma_f16(o[2 * ntp + 1], af, vbr + 2);
                }
            }
            __syncwarp();
        }

        // ---- pipeline: free slot, issue tile i+2, wait tile i+1 ----
        __syncthreads();
        if (i + 2 < NT) {
            int kb2 = (i + 2) * BKT;
            uint32_t kd = sb + (W_KS + slot * 4608) * 4;
            uint32_t vd = sb + (W_VS + slot * 4608) * 4;
            #pragma unroll
            for (int j = 0; j < 4; j++) {
                int key = kb2 + trow[j];
                cp16(kd + (trow[j] * 36 + (tsg[j] >> 1)) * 4, &kg[(size_t)key * HD + tsg[j]]);
                cp16(vd + (trow[j] * 36 + (tsg[j] >> 1)) * 4, &vg[(size_t)key * HD + tsg[j]]);
            }
        }
        CP_COMMIT();
        CP_WAIT1();
        __syncthreads();
    }

    l0 += __shfl_xor_sync(0xffffffff, l0, 1);
    l0 += __shfl_xor_sync(0xffffffff, l0, 2);
    l1 += __shfl_xor_sync(0xffffffff, l1, 1);
    l1 += __shfl_xor_sync(0xffffffff, l1, 2);
    float inv0 = 1.f / l0, inv1 = 1.f / l1;
    int r0 = q0 + wid * 16 + lr;
    __half* ob0 = g_att + ((size_t)(b * SEQ + r0)     * (NH * HD)) + h * HD;
    __half* ob1 = g_att + ((size_t)(b * SEQ + r0 + 8) * (NH * HD)) + h * HD;
    #pragma unroll
    for (int nt = 0; nt < 8; nt++) {
        int d = nt * 8 + 2 * lc;
        *reinterpret_cast<uint32_t*>(&ob0[d]) = f2h2(o[nt][0] * inv0, o[nt][1] * inv0);
        *reinterpret_cast<uint32_t*>(&ob1[d]) = f2h2(o[nt][2] * inv1, o[nt][3] * inv1);
    }
}

// ---------------- launch ----------------
extern "C" void kernel_launch(void* const* d_in, const int* in_sizes, int n_in,
                              void* d_out, int out_size)
{
    const float* x  = (const float*)d_in[0];
    const int*   pm = (const int*)  d_in[1];
    const float* qw = (const float*)d_in[2];
    const float* qb = (const float*)d_in[3];
    const float* kw = (const float*)d_in[4];
    const float* kb = (const float*)d_in[5];
    const float* vw = (const float*)d_in[6];
    const float* vb = (const float*)d_in[7];
    const float* ow = (const float*)d_in[8];
    const float* ob = (const float*)d_in[9];
    float* out = (float*)d_out;

    cudaFuncSetAttribute(qkv_kernel, cudaFuncAttributeMaxDynamicSharedMemorySize, GEMM_SMEM);
    cudaFuncSetAttribute(out_kernel, cudaFuncAttributeMaxDynamicSharedMemorySize, GEMM_SMEM);
    cudaFuncSetAttribute(attn_kernel, cudaFuncAttributeMaxDynamicSharedMemorySize,
                         ATTN_SMEM_BYTES);

    dim3 gp(32, 32, 5);
    prep_all<<<gp, dim3(32, 8)>>>((const float4*)x, pm, qw, kw, vw, ow);

    dim3 g1(DMODEL / 128, MTOK / 128, 3);
    qkv_kernel<<<g1, GT, GEMM_SMEM>>>(qb, kb, vb);

    dim3 g2(SEQ / BQ, BATCH * NH);
    attn_kernel<<<g2, 256, ATTN_SMEM_BYTES>>>(pm);

    dim3 g3(DMODEL / 128, MTOK / 128);
    out_kernel<<<g3, GT, GEMM_SMEM>>>(ob, out);
}

// round 16
// speedup vs baseline: 1.0732x; 1.0732x over previous
#include <cuda_runtime.h>
#include <cuda_fp16.h>
#include <math.h>
#include <stdint.h>

// ---------------- problem constants ----------------
#define DMODEL 1024
#define NH     16
#define HD     64
#define BATCH  2
#define SEQ    2048
#define MTOK   (BATCH*SEQ)        // 4096

// ---------------- scratch (device globals, all fp16) ----------------
__device__ __half g_x[MTOK*DMODEL];
__device__ __half g_q[BATCH*NH*SEQ*HD];
__device__ __half g_k[BATCH*NH*SEQ*HD];   // compacted rows per (b,h); tail zero
__device__ __half g_v[BATCH*NH*SEQ*HD];   // compacted rows per (b,h); tail zero
__device__ __half g_att[BATCH*SEQ*NH*HD];
__device__ __half g_wt[4*DMODEL*DMODEL];  // qwT,kwT,vwT,owT [N][K]
__device__ int    g_cidx[BATCH*SEQ];
__device__ int    g_cnt[BATCH];

// ---------------- helpers ----------------
__device__ __forceinline__ uint32_t f2h2(float a, float b) {
    __half2 h = __floats2half2_rn(a, b);
    return *reinterpret_cast<uint32_t*>(&h);
}
__device__ __forceinline__ uint32_t smem_u32(const void* p) {
    uint32_t a;
    asm("{ .reg .u64 t; cvta.to.shared.u64 t, %1; cvt.u32.u64 %0, t; }" : "=r"(a) : "l"(p));
    return a;
}
__device__ __forceinline__ void cp16(uint32_t dst, const void* src) {
    asm volatile("cp.async.cg.shared.global [%0], [%1], 16;" :: "r"(dst), "l"(src) : "memory");
}
#define CP_COMMIT() asm volatile("cp.async.commit_group;" ::: "memory")
#define CP_WAIT1()  asm volatile("cp.async.wait_group 1;"  ::: "memory")

__device__ __forceinline__ void mma_f16(float* d, const uint32_t* a, const uint32_t* b) {
    asm volatile(
        "mma.sync.aligned.m16n8k16.row.col.f32.f16.f16.f32 "
        "{%0,%1,%2,%3}, {%4,%5,%6,%7}, {%8,%9}, {%0,%1,%2,%3};"
        : "+f"(d[0]), "+f"(d[1]), "+f"(d[2]), "+f"(d[3])
        : "r"(a[0]), "r"(a[1]), "r"(a[2]), "r"(a[3]), "r"(b[0]), "r"(b[1]));
}
__device__ __forceinline__ void ldsm_x4(uint32_t* r, uint32_t addr) {
    asm volatile("ldmatrix.sync.aligned.m8n8.x4.shared.b16 {%0,%1,%2,%3}, [%4];"
                 : "=r"(r[0]), "=r"(r[1]), "=r"(r[2]), "=r"(r[3]) : "r"(addr));
}
__device__ __forceinline__ void ldsm_x4_trans(uint32_t* r, uint32_t addr) {
    asm volatile("ldmatrix.sync.aligned.m8n8.x4.trans.shared.b16 {%0,%1,%2,%3}, [%4];"
                 : "=r"(r[0]), "=r"(r[1]), "=r"(r[2]), "=r"(r[3]) : "r"(addr));
}

// ======================================================================
// prep_all: z=0..3 -> weight transpose to fp16 [N][K];
//           z=4    -> x -> fp16; blocks 0,1 also compact mask indices.
// ======================================================================
__global__ __launch_bounds__(256)
void prep_all(const float4* __restrict__ x, const int* __restrict__ pm,
              const float* __restrict__ qw, const float* __restrict__ kw,
              const float* __restrict__ vw, const float* __restrict__ ow)
{
    const int tx = threadIdx.x, ty = threadIdx.y;       // 32 x 8
    const int z = blockIdx.z;
    if (z < 4) {
        __shared__ float tile[32][33];
        const float* src = (z == 0) ? qw : (z == 1) ? kw : (z == 2) ? vw : ow;
        __half* dst = g_wt + (size_t)z * DMODEL * DMODEL;
        const int bx = blockIdx.x * 32, by = blockIdx.y * 32;
        #pragma unroll
        for (int i = 0; i < 32; i += 8)
            tile[ty + i][tx] = src[(size_t)(by + ty + i) * DMODEL + bx + tx];
        __syncthreads();
        #pragma unroll
        for (int i = 0; i < 32; i += 8)
            dst[(size_t)(bx + ty + i) * DMODEL + by + tx] = __float2half_rn(tile[tx][ty + i]);
        return;
    }
    const int t   = ty * 32 + tx;
    const int bid = blockIdx.y * 32 + blockIdx.x;
    #pragma unroll
    for (int j = 0; j < 4; j++) {
        int i = (bid * 4 + j) * 256 + t;
        float4 v = x[i];
        reinterpret_cast<uint2*>(g_x)[i] =
            make_uint2(f2h2(v.x, v.y), f2h2(v.z, v.w));
    }
    if (bid < BATCH) {
        __shared__ int wsum[8];
        const int b = bid;
        const int* row = pm + b * SEQ;
        const int lane = t & 31, w = t >> 5;
        int flags[8], cnt = 0;
        #pragma unroll
        for (int j = 0; j < 8; j++) { flags[j] = (row[t * 8 + j] == 0); cnt += flags[j]; }
        int inc = cnt;
        #pragma unroll
        for (int d = 1; d < 32; d <<= 1) {
            int v = __shfl_up_sync(0xffffffff, inc, d);
            if (lane >= d) inc += v;
        }
        if (lane == 31) wsum[w] = inc;
        __syncthreads();
        int woff = 0;
        for (int ww = 0; ww < w; ww++) woff += wsum[ww];
        int pos = woff + inc - cnt;
        #pragma unroll
        for (int j = 0; j < 8; j++)
            if (flags[j]) g_cidx[b * SEQ + pos++] = t * 8 + j;
        if (t == 255) g_cnt[b] = woff + inc;
    }
}

// ======================================================================
// GEMM fp16 (unchanged from R13): BM=BN=128, BK=64, 3-stage cp.async,
// 8 warps (2x4), warp tile 64x32, m16n8k16, ldmatrix fragments.
// MODE 0: Q; MODE 1: out (fp32); MODE 2: K/V compacted + zero tail.
// ======================================================================
#define GT 256
#define GSTG 3
#define ASTRIDE 36
#define TILE_W  (128 * ASTRIDE)       // 4608 words
#define STAGE_W (2 * TILE_W)          // 9216 words
#define GEMM_SMEM (GSTG * STAGE_W * 4)  // 110592 B

template<int MODE>
__device__ __forceinline__ void gemm_body(const __half* __restrict__ A,
                                          const __half* __restrict__ BT,
                                          const float* __restrict__ bias,
                                          void* __restrict__ Cv)
{
    extern __shared__ uint32_t sm[];
    const uint32_t sb = smem_u32(sm);

    const int t     = threadIdx.x;
    const int lane  = t & 31;
    const int warp  = t >> 5;
    const int warpM = warp >> 2;
    const int warpN = warp & 3;
    const int lr    = lane >> 2;
    const int lc    = lane & 3;
    const int m0    = blockIdx.y * 128;
    const int n0    = blockIdx.x * 128;

    int n_b = SEQ;
    int bB  = 0;
    if (MODE == 2) {
        bB  = m0 >> 11;
        n_b = g_cnt[bB];
        const int n_pad = (n_b + 63) & ~63;
        if ((m0 & (SEQ - 1)) >= n_pad) return;
    }

    const int lrow16 = lane & 15;
    const int lkw    = ((lane >> 4) & 1) * 4;

    const int lrow[4] = { (t+0)>>3, (t+256)>>3, (t+512)>>3, (t+768)>>3 };
    const int lsg [4] = { (t+0)&7,  (t+256)&7,  (t+512)&7,  (t+768)&7  };

    const __half* aptr[4];
    #pragma unroll
    for (int i = 0; i < 4; i++) {
        if (MODE == 2) {
            int s = (m0 & (SEQ - 1)) + lrow[i];
            int sc = s < n_b - 1 ? s : n_b - 1;
            int ridx = g_cidx[bB * SEQ + sc];
            aptr[i] = A + (size_t)(bB * SEQ + ridx) * DMODEL;
        } else {
            aptr[i] = A + (size_t)(m0 + lrow[i]) * DMODEL;
        }
    }

    float acc[4][4][4];
    #pragma unroll
    for (int mt = 0; mt < 4; mt++)
        #pragma unroll
        for (int nt = 0; nt < 4; nt++)
            #pragma unroll
            for (int c = 0; c < 4; c++) acc[mt][nt][c] = 0.f;

    #pragma unroll
    for (int s = 0; s < 2; s++) {
        uint32_t base = sb + s * STAGE_W * 4;
        #pragma unroll
        for (int i = 0; i < 4; i++) {
            cp16(base + (lrow[i] * ASTRIDE + lsg[i] * 4) * 4,
                 aptr[i] + s * 64 + lsg[i] * 8);
            cp16(base + (TILE_W + lrow[i] * ASTRIDE + lsg[i] * 4) * 4,
                 &BT[(size_t)(n0 + lrow[i]) * DMODEL + s * 64 + lsg[i] * 8]);
        }
        CP_COMMIT();
    }

    const int NCH = DMODEL / 64;
    for (int c = 0; c < NCH; c++) {
        CP_WAIT1();
        __syncthreads();

        if (c + 2 < NCH) {
            uint32_t base = sb + ((c + 2) % GSTG) * STAGE_W * 4;
            int k0 = (c + 2) * 64;
            #pragma unroll
            for (int i = 0; i < 4; i++) {
                cp16(base + (lrow[i] * ASTRIDE + lsg[i] * 4) * 4,
                     aptr[i] + k0 + lsg[i] * 8);
                cp16(base + (TILE_W + lrow[i] * ASTRIDE + lsg[i] * 4) * 4,
                     &BT[(size_t)(n0 + lrow[i]) * DMODEL + k0 + lsg[i] * 8]);
            }
        }
        CP_COMMIT();

        const uint32_t asb = sb + ((c % GSTG) * STAGE_W) * 4;
        const uint32_t bsb = asb + TILE_W * 4;
        #pragma unroll
        for (int p = 0; p < 4; p++) {
            uint32_t af[4][4], bq[2][4];
            #pragma unroll
            for (int mt = 0; mt < 4; mt++)
                ldsm_x4(af[mt], asb + ((warpM * 64 + mt * 16 + lrow16) * ASTRIDE
                                       + p * 8 + lkw) * 4);
            #pragma unroll
            for (int ntp = 0; ntp < 2; ntp++)
                ldsm_x4(bq[ntp], bsb + ((warpN * 32 + ntp * 16 + lrow16) * ASTRIDE
                                        + p * 8 + lkw) * 4);
            #pragma unroll
            for (int mt = 0; mt < 4; mt++) {
                #pragma unroll
                for (int ntp = 0; ntp < 2; ntp++) {
                    uint32_t b0[2] = { bq[ntp][0], bq[ntp][2] };
                    uint32_t b1[2] = { bq[ntp][1], bq[ntp][3] };
                    mma_f16(acc[mt][2 * ntp + 0], af[mt], b0);
                    mma_f16(acc[mt][2 * ntp + 1], af[mt], b1);
                }
            }
        }
    }

    #pragma unroll
    for (int mt = 0; mt < 4; mt++) {
        #pragma unroll
        for (int nt = 0; nt < 4; nt++) {
            int n = n0 + warpN * 32 + nt * 8 + 2 * lc;
            float bia0 = bias[n], bia1 = bias[n + 1];
            #pragma unroll
            for (int half_ = 0; half_ < 2; half_++) {
                int m = m0 + warpM * 64 + mt * 16 + lr + half_ * 8;
                float v0 = acc[mt][nt][half_ * 2 + 0] + bia0;
                float v1 = acc[mt][nt][half_ * 2 + 1] + bia1;
                if (MODE == 1) {
                    float* C = (float*)Cv;
                    *reinterpret_cast<float2*>(&C[(size_t)m * DMODEL + n]) = make_float2(v0, v1);
                } else {
                    int b = m >> 11, s = m & (SEQ - 1);
                    if (MODE == 2 && s >= n_b) { v0 = 0.f; v1 = 0.f; }
                    int h = n >> 6,  d = n & (HD - 1);
                    __half* C = (__half*)Cv;
                    *reinterpret_cast<uint32_t*>(
                        &C[(((size_t)(b * NH + h) * SEQ) + s) * HD + d]) = f2h2(v0, v1);
                }
            }
        }
    }
}

__global__ __launch_bounds__(GT, 2)
void qkv_kernel(const float* __restrict__ qb, const float* __restrict__ kb,
                const float* __restrict__ vb)
{
    if (blockIdx.z == 0)      gemm_body<0>(g_x, g_wt + 0 * DMODEL * DMODEL, qb, g_q);
    else if (blockIdx.z == 1) gemm_body<2>(g_x, g_wt + 1 * DMODEL * DMODEL, kb, g_k);
    else                      gemm_body<2>(g_x, g_wt + 2 * DMODEL * DMODEL, vb, g_v);
}

__global__ __launch_bounds__(GT, 2)
void out_kernel(const float* __restrict__ ob, float* __restrict__ out)
{
    gemm_body<1>(g_att, g_wt + 3 * DMODEL * DMODEL, ob, out);
}

// ======================================================================
// FlashAttention fp16 over DENSE compacted K/V (R13 structure).
// BQ=128, 8 warps, BKEY=64, m16n8k16. P stays in REGISTERS: the S
// C-fragment repacks directly into the PV A-fragment (FA2 trick) --
// no P smem store, no P ldmatrix, no syncwarp.
// ======================================================================
#define BQ   128
#define BKEY 64
#define W_QP 0                          // 128*36
#define W_KS 4608                       // 2 x 64*36
#define W_VS 9216                       // 2 x 64*36
#define ATTN_W 13824
#define ATTN_SMEM_BYTES (ATTN_W * 4)    // 55296 B

__global__ __launch_bounds__(256, 2)
void attn_kernel(const int* __restrict__ pmask)
{
    extern __shared__ uint32_t sm[];
    const uint32_t sb = smem_u32(sm);

    const int bh = blockIdx.y;
    const int b  = bh >> 4;
    const int h  = bh & (NH - 1);
    const int q0 = blockIdx.x * BQ;
    const int t    = threadIdx.x;
    const int lane = t & 31;
    const int wid  = t >> 5;
    const int lr   = lane >> 2;
    const int lc   = lane & 3;
    const int lrow16 = lane & 15;
    const int lkw    = ((lane >> 4) & 1) * 4;

    const __half* qg = g_q + (size_t)bh * SEQ * HD;
    const __half* kg = g_k + (size_t)bh * SEQ * HD;
    const __half* vg = g_v + (size_t)bh * SEQ * HD;
    const int     n_b  = g_cnt[b];
    const int     NT   = (n_b + BKEY - 1) / BKEY;

    const int trow[2] = { (t+0)>>3, (t+256)>>3 };
    const int tho [2] = { ((t+0)&7)*8, ((t+256)&7)*8 };

    // ---- prologue: Q + tile0, tile1 ----
    #pragma unroll
    for (int i = 0; i < 4; i++) {
        int f = t + i * 256, row = f >> 3, ho = (f & 7) * 8;
        cp16(sb + (W_QP + row * 36 + (ho >> 1)) * 4, &qg[(size_t)(q0 + row) * HD + ho]);
    }
    #pragma unroll
    for (int j = 0; j < 2; j++) {
        cp16(sb + (W_KS + trow[j] * 36 + (tho[j] >> 1)) * 4, &kg[(size_t)trow[j] * HD + tho[j]]);
        cp16(sb + (W_VS + trow[j] * 36 + (tho[j] >> 1)) * 4, &vg[(size_t)trow[j] * HD + tho[j]]);
    }
    CP_COMMIT();
    if (NT > 1) {
        #pragma unroll
        for (int j = 0; j < 2; j++) {
            int key = BKEY + trow[j];
            cp16(sb + (W_KS + 2304 + trow[j] * 36 + (tho[j] >> 1)) * 4, &kg[(size_t)key * HD + tho[j]]);
            cp16(sb + (W_VS + 2304 + trow[j] * 36 + (tho[j] >> 1)) * 4, &vg[(size_t)key * HD + tho[j]]);
        }
    }
    CP_COMMIT();
    CP_WAIT1();
    __syncthreads();

    // ---- Q fragments via ldmatrix ----
    uint32_t qf[4][4];
    {
        uint32_t qpb = sb + W_QP * 4;
        #pragma unroll
        for (int ks = 0; ks < 4; ks++)
            ldsm_x4(qf[ks], qpb + ((wid * 16 + lrow16) * 36 + ks * 8 + lkw) * 4);
    }

    const int vmi = lane >> 3, vli = lane & 7;
    const int vrow = ((vmi & 1) ? 8 : 0) + vli;
    const int vcol = (vmi >> 1) ? 4 : 0;

    float o[8][4];
    #pragma unroll
    for (int nt = 0; nt < 8; nt++)
        #pragma unroll
        for (int c = 0; c < 4; c++) o[nt][c] = 0.f;
    float l0 = 0.f, l1 = 0.f;

    for (int i = 0; i < NT; i++) {
        const int slot = i & 1;
        const int kb = i * BKEY;
        const uint32_t ksb = sb + (W_KS + slot * 2304) * 4;
        const uint32_t vsb = sb + (W_VS + slot * 2304) * 4;

        // ---- S = Q K^T ----
        float s[8][4];
        #pragma unroll
        for (int nt = 0; nt < 8; nt++)
            #pragma unroll
            for (int c = 0; c < 4; c++) s[nt][c] = 0.f;
        #pragma unroll
        for (int ks = 0; ks < 4; ks++) {
            uint32_t kq[4][4];
            #pragma unroll
            for (int ntp = 0; ntp < 4; ntp++)
                ldsm_x4(kq[ntp], ksb + ((ntp * 16 + lrow16) * 36 + ks * 8 + lkw) * 4);
            #pragma unroll
            for (int ntp = 0; ntp < 4; ntp++) {
                uint32_t b0[2] = { kq[ntp][0], kq[ntp][2] };
                uint32_t b1[2] = { kq[ntp][1], kq[ntp][3] };
                mma_f16(s[2 * ntp + 0], qf[ks], b0);
                mma_f16(s[2 * ntp + 1], qf[ks], b1);
            }
        }

        // ---- p = exp(s/8) (tail -> 0); accumulate l; repack into PV
        //      A-fragments in registers (no smem round-trip) ----
        uint32_t pf[4][4];
        #pragma unroll
        for (int nt = 0; nt < 8; nt++) {
            float ma0 = (kb + nt * 8 + 2 * lc     < n_b) ? 0.0f : -1e30f;
            float ma1 = (kb + nt * 8 + 2 * lc + 1 < n_b) ? 0.0f : -1e30f;
            float p0 = __expf(fmaf(s[nt][0], 0.125f, ma0));
            float p1 = __expf(fmaf(s[nt][1], 0.125f, ma1));
            float p2 = __expf(fmaf(s[nt][2], 0.125f, ma0));
            float p3 = __expf(fmaf(s[nt][3], 0.125f, ma1));
            l0 += p0 + p1;
            l1 += p2 + p3;
            int kt = nt >> 1, hi = (nt & 1) * 2;
            pf[kt][hi + 0] = f2h2(p0, p1);   // rows lr,   keys (a0 / a2)
            pf[kt][hi + 1] = f2h2(p2, p3);   // rows lr+8, keys (a1 / a3)
        }

        // ---- O += P V : P from registers, V via ldmatrix.trans ----
        #pragma unroll
        for (int kt = 0; kt < 4; kt++) {
            #pragma unroll
            for (int ntp = 0; ntp < 4; ntp++) {
                uint32_t vbr[4];
                uint32_t addr = vsb + (((kt * 16 + vrow) * 36) + ntp * 8 + vcol) * 4;
                ldsm_x4_trans(vbr, addr);
                mma_f16(o[2 * ntp + 0], pf[kt], vbr + 0);
                mma_f16(o[2 * ntp + 1], pf[kt], vbr + 2);
            }
        }

        // ---- pipeline: free slot, issue tile i+2, wait tile i+1 ----
        __syncthreads();
        if (i + 2 < NT) {
            int kb2 = (i + 2) * BKEY;
            uint32_t kd = sb + (W_KS + slot * 2304) * 4;
            uint32_t vd = sb + (W_VS + slot * 2304) * 4;
            #pragma unroll
            for (int j = 0; j < 2; j++) {
                int key = kb2 + trow[j];
                cp16(kd + (trow[j] * 36 + (tho[j] >> 1)) * 4, &kg[(size_t)key * HD + tho[j]]);
                cp16(vd + (trow[j] * 36 + (tho[j] >> 1)) * 4, &vg[(size_t)key * HD + tho[j]]);
            }
        }
        CP_COMMIT();
        CP_WAIT1();
        __syncthreads();
    }

    // ---- epilogue ----
    l0 += __shfl_xor_sync(0xffffffff, l0, 1);
    l0 += __shfl_xor_sync(0xffffffff, l0, 2);
    l1 += __shfl_xor_sync(0xffffffff, l1, 1);
    l1 += __shfl_xor_sync(0xffffffff, l1, 2);
    float inv0 = 1.f / l0, inv1 = 1.f / l1;
    int r0 = q0 + wid * 16 + lr;
    __half* ob0 = g_att + ((size_t)(b * SEQ + r0)     * (NH * HD)) + h * HD;
    __half* ob1 = g_att + ((size_t)(b * SEQ + r0 + 8) * (NH * HD)) + h * HD;
    #pragma unroll
    for (int nt = 0; nt < 8; nt++) {
        int d = nt * 8 + 2 * lc;
        *reinterpret_cast<uint32_t*>(&ob0[d]) = f2h2(o[nt][0] * inv0, o[nt][1] * inv0);
        *reinterpret_cast<uint32_t*>(&ob1[d]) = f2h2(o[nt][2] * inv1, o[nt][3] * inv1);
    }
}

// ---------------- launch ----------------
extern "C" void kernel_launch(void* const* d_in, const int* in_sizes, int n_in,
                              void* d_out, int out_size)
{
    const float* x  = (const float*)d_in[0];
    const int*   pm = (const int*)  d_in[1];
    const float* qw = (const float*)d_in[2];
    const float* qb = (const float*)d_in[3];
    const float* kw = (const float*)d_in[4];
    const float* kb = (const float*)d_in[5];
    const float* vw = (const float*)d_in[6];
    const float* vb = (const float*)d_in[7];
    const float* ow = (const float*)d_in[8];
    const float* ob = (const float*)d_in[9];
    float* out = (float*)d_out;

    cudaFuncSetAttribute(qkv_kernel, cudaFuncAttributeMaxDynamicSharedMemorySize, GEMM_SMEM);
    cudaFuncSetAttribute(out_kernel, cudaFuncAttributeMaxDynamicSharedMemorySize, GEMM_SMEM);
    cudaFuncSetAttribute(attn_kernel, cudaFuncAttributeMaxDynamicSharedMemorySize,
                         ATTN_SMEM_BYTES);

    dim3 gp(32, 32, 5);
    prep_all<<<gp, dim3(32, 8)>>>((const float4*)x, pm, qw, kw, vw, ow);

    dim3 g1(DMODEL / 128, MTOK / 128, 3);
    qkv_kernel<<<g1, GT, GEMM_SMEM>>>(qb, kb, vb);

    dim3 g2(SEQ / BQ, BATCH * NH);
    attn_kernel<<<g2, 256, ATTN_SMEM_BYTES>>>(pm);

    dim3 g3(DMODEL / 128, MTOK / 128);
    out_kernel<<<g3, GT, GEMM_SMEM>>>(ob, out);
}